// round 15
// baseline (speedup 1.0000x reference)
#include <cuda_runtime.h>
#include <cuda_fp16.h>
#include <math.h>
#include <stdint.h>

// ---------------------------------------------------------------------------
// Problem constants
// ---------------------------------------------------------------------------
#define DIMV 512
#define BV   16
#define LV   2048
#define NROWS (BV * LV)      // 32768
#define HIDV 2048
#define GHID 128
#define LN_EPS 1e-5f

// ---------------------------------------------------------------------------
// Scratch (device globals — no allocations allowed)
// ---------------------------------------------------------------------------
__device__ __half g_mixg_h  [(size_t)NROWS * DIMV];
__device__ __half g_mixed2_h[(size_t)NROWS * DIMV];
__device__ __half g_h2_h    [(size_t)NROWS * DIMV];
__device__ __half g_hid_h   [(size_t)NROWS * HIDV];
__device__ float g_x1   [(size_t)NROWS * DIMV];
__device__ float g_ct   [BV * DIMV];               // column sums (atomic)
__device__ float g_gate [BV * DIMV];
__device__ __half g_wmixT_h[DIMV * DIMV];          // [c][o]  (wmix.T)
__device__ __half g_wout_h [DIMV * DIMV];          // [k][m] as given
__device__ __half g_w1_h   [(size_t)DIMV * HIDV];  // [k][m] as given
__device__ __half g_w2_h   [(size_t)HIDV * DIMV];  // [k][m] as given

// ---------------------------------------------------------------------------
// Helpers
// ---------------------------------------------------------------------------
__device__ __forceinline__ uint32_t smem_u32(const void* p) {
    uint32_t a;
    asm("{ .reg .u64 t; cvta.to.shared.u64 t, %1; cvt.u32.u64 %0, t; }" : "=r"(a) : "l"(p));
    return a;
}
__device__ __forceinline__ void cp16(void* sdst, const void* gsrc) {
    uint32_t s = smem_u32(sdst);
    asm volatile("cp.async.cg.shared.global [%0], [%1], 16;" :: "r"(s), "l"(gsrc));
}
#define CP_COMMIT() asm volatile("cp.async.commit_group;" ::: "memory")
#define CP_WAIT(N)  asm volatile("cp.async.wait_group %0;" :: "n"(N) : "memory")

__device__ __forceinline__ void ldsm4(uint32_t* r, const void* p) {
    uint32_t a = smem_u32(p);
    asm volatile("ldmatrix.sync.aligned.m8n8.x4.shared.b16 {%0,%1,%2,%3}, [%4];"
        : "=r"(r[0]), "=r"(r[1]), "=r"(r[2]), "=r"(r[3]) : "r"(a));
}
__device__ __forceinline__ void ldsm4t(uint32_t* r, const void* p) {
    uint32_t a = smem_u32(p);
    asm volatile("ldmatrix.sync.aligned.m8n8.x4.trans.shared.b16 {%0,%1,%2,%3}, [%4];"
        : "=r"(r[0]), "=r"(r[1]), "=r"(r[2]), "=r"(r[3]) : "r"(a));
}
// fp16 mma with fp16 accumulators
__device__ __forceinline__ void mma16816h(uint32_t* c, const uint32_t* a, const uint32_t* b) {
    asm volatile("mma.sync.aligned.m16n8k16.row.col.f16.f16.f16.f16 "
        "{%0,%1}, {%2,%3,%4,%5}, {%6,%7}, {%0,%1};"
        : "+r"(c[0]), "+r"(c[1])
        : "r"(a[0]), "r"(a[1]), "r"(a[2]), "r"(a[3]), "r"(b[0]), "r"(b[1]));
}
__device__ __forceinline__ uint32_t hmul2u(uint32_t a, uint32_t b) {
    __half2 x = *reinterpret_cast<__half2*>(&a);
    __half2 y = *reinterpret_cast<__half2*>(&b);
    __half2 r = __hmul2(x, y);
    return *reinterpret_cast<uint32_t*>(&r);
}

__device__ __forceinline__ float gelu_f(float v) {
    return 0.5f * v * (1.0f + erff(v * 0.70710678118654752f));
}
__device__ __forceinline__ uint32_t pack_h2(float a, float b) {
    __half2 h = __floats2half2_rn(a, b);
    return *reinterpret_cast<uint32_t*>(&h);
}
__device__ __forceinline__ float2 unpack_h2(uint32_t u) {
    __half2 h = *reinterpret_cast<__half2*>(&u);
    return __half22float2(h);
}

// ---------------------------------------------------------------------------
// fp16 mma.sync GEMM (f16 acc): 128x128 tile, BK=32, 8 warps (4x2),
//   warp tile 32x64, 3-stage cp.async, 3 CTAs/SM.  (R13 champion config)
//   GATE: multiply A fragments by per-(batch,k) gate (fp16).
//   EPI 0: f16 out = acc + bias; ALSO column-sum tile -> atomicAdd g_ct
//   EPI 1: f16 out = gelu(acc + bias)
//   EPI 2: f32 out = resid + (acc + bias) * ls
// ---------------------------------------------------------------------------
#define AS_STRIDE 40
#define BS_STRIDE 136
#define AS_STAGE  (128 * AS_STRIDE)
#define BS_STAGE  (32 * BS_STRIDE)
#define SGATE_OFF (3 * (AS_STAGE + BS_STAGE))          // half units
#define GEMM_SMEM ((SGATE_OFF + 512) * 2)              // 57856 bytes

template<int EPI, bool GATE>
__global__ void __launch_bounds__(256, 3)
mma_gemm(const __half* __restrict__ A, const __half* __restrict__ W,
         const float* __restrict__ bias, void* __restrict__ Cout, int K, int M,
         const float* __restrict__ resid, const float* __restrict__ ls,
         const float* __restrict__ gate, float* __restrict__ ctsum) {
    extern __shared__ __half sm[];
    __half* As = sm;
    __half* Bs = sm + 3 * AS_STAGE;
    uint32_t* sgate = (uint32_t*)(sm + SGATE_OFF);

    int tid = threadIdx.x, wid = tid >> 5, lane = tid & 31;
    int wm = wid & 3, wn = wid >> 2;
    size_t rowBase = (size_t)blockIdx.y * 128;
    int colBase = blockIdx.x * 128;
    const __half* Abase = A + rowBase * (size_t)K;

    if (GATE) {
        int b = (int)(rowBase >> 11);
        if (tid < 256) {
            float g0 = gate[b * DIMV + tid * 2];
            float g1 = gate[b * DIMV + tid * 2 + 1];
            sgate[tid] = pack_h2(g0, g1);
        }
    }

    auto prefetch = [&](int cc, int st) {
        int k0 = cc << 5;
        __half* as = As + st * AS_STAGE;
        __half* bs = Bs + st * BS_STAGE;
        #pragma unroll
        for (int i = 0; i < 2; i++) {
            int q = (i << 8) + tid;
            int r = q >> 2, c = (q & 3) << 3;
            cp16(as + r * AS_STRIDE + c, Abase + (size_t)r * K + k0 + c);
            int r2 = q >> 4, c2 = (q & 15) << 3;
            cp16(bs + r2 * BS_STRIDE + c2, W + (size_t)(k0 + r2) * M + colBase + c2);
        }
    };

    uint32_t acc[2][8][2];
    #pragma unroll
    for (int mi = 0; mi < 2; mi++)
        #pragma unroll
        for (int nj = 0; nj < 8; nj++) { acc[mi][nj][0] = 0u; acc[mi][nj][1] = 0u; }

    int nch = K >> 5;
    prefetch(0, 0); CP_COMMIT();
    prefetch(1, 1); CP_COMMIT();

    int la = lane & 15, lb = lane >> 4;
    int tp = lane & 3;
    int st = 0, stw = 2;
    #pragma unroll 1
    for (int cc = 0; cc < nch; cc++) {
        CP_WAIT(1);
        __syncthreads();
        if (cc + 2 < nch) prefetch(cc + 2, stw);
        CP_COMMIT();

        __half* as = As + st * AS_STAGE;
        __half* bs = Bs + st * BS_STAGE;
        #pragma unroll
        for (int ks = 0; ks < 2; ks++) {
            uint32_t af[2][4], bf[4][4];
            #pragma unroll
            for (int mi = 0; mi < 2; mi++)
                ldsm4(af[mi], as + (wm * 32 + mi * 16 + la) * AS_STRIDE + ks * 16 + lb * 8);
            if (GATE) {
                uint32_t gp0 = sgate[cc * 16 + ks * 8 + tp];
                uint32_t gp1 = sgate[cc * 16 + ks * 8 + tp + 4];
                #pragma unroll
                for (int mi = 0; mi < 2; mi++) {
                    af[mi][0] = hmul2u(af[mi][0], gp0);
                    af[mi][1] = hmul2u(af[mi][1], gp0);
                    af[mi][2] = hmul2u(af[mi][2], gp1);
                    af[mi][3] = hmul2u(af[mi][3], gp1);
                }
            }
            #pragma unroll
            for (int ng = 0; ng < 4; ng++)
                ldsm4t(bf[ng], bs + (ks * 16 + la) * BS_STRIDE + wn * 64 + ng * 16 + lb * 8);
            #pragma unroll
            for (int mi = 0; mi < 2; mi++)
                #pragma unroll
                for (int nj = 0; nj < 8; nj++)
                    mma16816h(acc[mi][nj], af[mi], &bf[nj >> 1][(nj & 1) * 2]);
        }
        st = (st == 2) ? 0 : st + 1;
        stw = (stw == 2) ? 0 : stw + 1;
    }

    // ---- epilogue ----
    int tg = lane >> 2;
    float csum[8][2];                 // per-thread column partials (EPI0)
    if (EPI == 0) {
        #pragma unroll
        for (int nj = 0; nj < 8; nj++) { csum[nj][0] = 0.f; csum[nj][1] = 0.f; }
    }
    #pragma unroll
    for (int mi = 0; mi < 2; mi++) {
        size_t r0 = rowBase + (size_t)(wm * 32 + mi * 16 + tg);
        size_t r1 = r0 + 8;
        #pragma unroll
        for (int nj = 0; nj < 8; nj++) {
            int col = colBase + wn * 64 + nj * 8 + tp * 2;
            float2 v0 = unpack_h2(acc[mi][nj][0]);
            float2 v1 = unpack_h2(acc[mi][nj][1]);
            float b0 = __ldg(&bias[col]), b1 = __ldg(&bias[col + 1]);
            if (EPI == 0 || EPI == 1) {
                float a0 = v0.x + b0, a1 = v0.y + b1;
                float a2 = v1.x + b0, a3 = v1.y + b1;
                if (EPI == 1) { a0 = gelu_f(a0); a1 = gelu_f(a1); a2 = gelu_f(a2); a3 = gelu_f(a3); }
                if (EPI == 0) { csum[nj][0] += a0 + a2; csum[nj][1] += a1 + a3; }
                __half* op = (__half*)Cout;
                *(uint32_t*)(op + r0 * M + col) = pack_h2(a0, a1);
                *(uint32_t*)(op + r1 * M + col) = pack_h2(a2, a3);
            } else {
                float s0 = __ldg(&ls[col]), s1 = __ldg(&ls[col + 1]);
                float* op = (float*)Cout;
                float2 rr0 = *(const float2*)(resid + r0 * M + col);
                float2 rr1 = *(const float2*)(resid + r1 * M + col);
                float2 o0 = make_float2(rr0.x + (v0.x + b0) * s0, rr0.y + (v0.y + b1) * s1);
                float2 o1 = make_float2(rr1.x + (v1.x + b0) * s0, rr1.y + (v1.y + b1) * s1);
                *(float2*)(op + r0 * M + col) = o0;
                *(float2*)(op + r1 * M + col) = o1;
            }
        }
    }
    if (EPI == 0) {
        // reduce column partials across the CTA via smem, then 1 atomic per col
        float* scol = (float*)sm;     // 128 floats (smem free after mainloop)
        __syncthreads();
        if (tid < 128) scol[tid] = 0.f;
        __syncthreads();
        #pragma unroll
        for (int nj = 0; nj < 8; nj++) {
            int c0 = wn * 64 + nj * 8 + tp * 2;
            atomicAdd(&scol[c0],     csum[nj][0]);
            atomicAdd(&scol[c0 + 1], csum[nj][1]);
        }
        __syncthreads();
        if (tid < 128) {
            int b = (int)(rowBase >> 11);
            atomicAdd(&ctsum[b * DIMV + colBase + tid], scol[tid]);
        }
    }
}

// ---------------------------------------------------------------------------
// Standalone LayerNorm (LN2): fp32 in -> fp16 out, 1 block/row.
// ---------------------------------------------------------------------------
__device__ __forceinline__ void block_reduce_2(float& s, float& sq) {
    #pragma unroll
    for (int off = 16; off > 0; off >>= 1) {
        s  += __shfl_down_sync(0xffffffffu, s,  off);
        sq += __shfl_down_sync(0xffffffffu, sq, off);
    }
    __shared__ float sh[8];
    int w = threadIdx.x >> 5, lane = threadIdx.x & 31;
    if (lane == 0) { sh[w] = s; sh[4 + w] = sq; }
    __syncthreads();
    if (threadIdx.x < 32) {
        float a = (lane < 4) ? sh[lane] : 0.f;
        float b = (lane < 4) ? sh[4 + lane] : 0.f;
        #pragma unroll
        for (int off = 2; off > 0; off >>= 1) {
            a += __shfl_down_sync(0xffffffffu, a, off);
            b += __shfl_down_sync(0xffffffffu, b, off);
        }
        if (lane == 0) { sh[0] = a; sh[1] = b; }
    }
    __syncthreads();
    s = sh[0]; sq = sh[1];
}

__global__ void ln_kernel(const float* __restrict__ x, const float* __restrict__ g,
                          const float* __restrict__ b, __half* __restrict__ out) {
    size_t row = blockIdx.x;
    float4 v = ((const float4*)(x + row * DIMV))[threadIdx.x];
    float s  = v.x + v.y + v.z + v.w;
    float sq = v.x * v.x + v.y * v.y + v.z * v.z + v.w * v.w;
    block_reduce_2(s, sq);
    float mu  = s * (1.0f / DIMV);
    float var = sq * (1.0f / DIMV) - mu * mu;
    float r   = rsqrtf(var + LN_EPS);
    float4 gg = ((const float4*)g)[threadIdx.x];
    float4 bb = ((const float4*)b)[threadIdx.x];
    float o0 = (v.x - mu) * r * gg.x + bb.x;
    float o1 = (v.y - mu) * r * gg.y + bb.y;
    float o2 = (v.z - mu) * r * gg.z + bb.z;
    float o3 = (v.w - mu) * r * gg.w + bb.w;
    *(uint2*)(out + row * DIMV + threadIdx.x * 4) = make_uint2(pack_h2(o0, o1), pack_h2(o2, o3));
}

// ---------------------------------------------------------------------------
// Fused LN1 + depthwise conv (k=3,5,7 avg) + GELU -> fp16.
// ---------------------------------------------------------------------------
#define CONV_L 128
#define CHALO 3
#define CROWS (CONV_L + 2 * CHALO)              // 134
#define LNCONV_SMEM (CROWS * DIMV * 2)          // 137216 bytes

__global__ void __launch_bounds__(256, 1)
ln_conv_kernel(const float* __restrict__ x,
               const float* __restrict__ g, const float* __restrict__ bb_,
               const float* __restrict__ w3, const float* __restrict__ b3,
               const float* __restrict__ w5, const float* __restrict__ b5,
               const float* __restrict__ w7, const float* __restrict__ b7,
               __half* __restrict__ out) {
    extern __shared__ __half tile[];            // [CROWS][DIMV]
    int tid = threadIdx.x, wid = tid >> 5, lane = tid & 31;
    int l0 = blockIdx.x * CONV_L;
    int b  = blockIdx.y;

    for (int r = wid; r < CROWS; r += 8) {
        int l = l0 - CHALO + r;
        if (l < 0 || l >= LV) continue;
        const float4* xr = (const float4*)(x + ((size_t)(b * LV + l) << 9));
        float4 v[4];
        float s = 0.f, sq = 0.f;
        #pragma unroll
        for (int i = 0; i < 4; i++) {
            v[i] = xr[lane + 32 * i];
            s  += v[i].x + v[i].y + v[i].z + v[i].w;
            sq += v[i].x * v[i].x + v[i].y * v[i].y + v[i].z * v[i].z + v[i].w * v[i].w;
        }
        #pragma unroll
        for (int off = 16; off > 0; off >>= 1) {
            s  += __shfl_xor_sync(0xffffffffu, s,  off);
            sq += __shfl_xor_sync(0xffffffffu, sq, off);
        }
        float mu  = s * (1.0f / DIMV);
        float var = sq * (1.0f / DIMV) - mu * mu;
        float rs  = rsqrtf(var + LN_EPS);
        #pragma unroll
        for (int i = 0; i < 4; i++) {
            int c = (lane + 32 * i) * 4;
            float4 gg = ((const float4*)g)[lane + 32 * i];
            float4 bv = ((const float4*)bb_)[lane + 32 * i];
            float o0 = (v[i].x - mu) * rs * gg.x + bv.x;
            float o1 = (v[i].y - mu) * rs * gg.y + bv.y;
            float o2 = (v[i].z - mu) * rs * gg.z + bv.z;
            float o3 = (v[i].w - mu) * rs * gg.w + bv.w;
            *(uint2*)&tile[r * DIMV + c] = make_uint2(pack_h2(o0, o1), pack_h2(o2, o3));
        }
    }
    __syncthreads();

    int c = tid * 2;
    float t0[7], t1[7];
    #pragma unroll
    for (int j = 0; j < 7; j++) { t0[j] = w7[c * 7 + j]; t1[j] = w7[(c + 1) * 7 + j]; }
    #pragma unroll
    for (int j = 1; j <= 5; j++) { t0[j] += w5[c * 5 + (j - 1)]; t1[j] += w5[(c + 1) * 5 + (j - 1)]; }
    #pragma unroll
    for (int j = 2; j <= 4; j++) { t0[j] += w3[c * 3 + (j - 2)]; t1[j] += w3[(c + 1) * 3 + (j - 2)]; }
    float base0 = b3[c] + b5[c] + b7[c];
    float base1 = b3[c + 1] + b5[c + 1] + b7[c + 1];

    #pragma unroll 2
    for (int il = 0; il < CONV_L; il++) {
        int l = l0 + il;
        float a0 = base0, a1 = base1;
        #pragma unroll
        for (int j = 0; j < 7; j++) {
            int ll = l + j - 3;
            if (ll >= 0 && ll < LV) {
                uint32_t u = *(uint32_t*)&tile[(il + j) * DIMV + c];
                float2 hv = unpack_h2(u);
                a0 += t0[j] * hv.x;
                a1 += t1[j] * hv.y;
            }
        }
        *(uint32_t*)(out + ((size_t)(b * LV + l) << 9) + c) =
            pack_h2(gelu_f(a0 * (1.0f / 3.0f)), gelu_f(a1 * (1.0f / 3.0f)));
    }
}

// ---------------------------------------------------------------------------
// Weight prep
// ---------------------------------------------------------------------------
__global__ void transpose_h_kernel(const float* __restrict__ in, __half* __restrict__ out,
                                   int R, int C) {
    __shared__ float t[32][33];
    int c0 = blockIdx.x * 32, r0 = blockIdx.y * 32;
    int tx = threadIdx.x, ty = threadIdx.y;
    #pragma unroll
    for (int i = 0; i < 32; i += 8)
        t[ty + i][tx] = in[(size_t)(r0 + ty + i) * C + c0 + tx];
    __syncthreads();
    #pragma unroll
    for (int i = 0; i < 32; i += 8)
        out[(size_t)(c0 + ty + i) * R + r0 + tx] = __float2half_rn(t[tx][ty + i]);
}

#define WOUT_N (DIMV * DIMV)          // 262144
#define W1_N   (DIMV * HIDV)          // 1048576
__global__ void wconv_all_kernel(const float* __restrict__ wout, const float* __restrict__ w1,
                                 const float* __restrict__ w2,
                                 __half* __restrict__ o_wout, __half* __restrict__ o_w1,
                                 __half* __restrict__ o_w2) {
    size_t i = ((size_t)blockIdx.x * 256 + threadIdx.x) * 4;
    const float* src; __half* dst; size_t off;
    if (i < WOUT_N)              { src = wout; dst = o_wout; off = i; }
    else if (i < WOUT_N + W1_N)  { src = w1;   dst = o_w1;   off = i - WOUT_N; }
    else                         { src = w2;   dst = o_w2;   off = i - WOUT_N - W1_N; }
    float4 v = *(const float4*)(src + off);
    *(uint2*)(dst + off) = make_uint2(pack_h2(v.x, v.y), pack_h2(v.z, v.w));
}

// ---------------------------------------------------------------------------
// zero g_ct before gemm0's epilogue atomics
// ---------------------------------------------------------------------------
__global__ void zero_kernel(float* p, int n) {
    int i = blockIdx.x * 256 + threadIdx.x;
    if (i < n) p[i] = 0.f;
}

// ---------------------------------------------------------------------------
// gate MLP (ct already fully reduced by gemm0 epilogue)
// ---------------------------------------------------------------------------
__global__ void gate_kernel(const float* __restrict__ ct,
                            const float* __restrict__ w1, const float* __restrict__ b1,
                            const float* __restrict__ w2, const float* __restrict__ b2,
                            float* __restrict__ gate) {
    __shared__ float sct[DIMV];
    __shared__ float shid[GHID];
    int b = blockIdx.x, t = threadIdx.x;
    for (int i = t; i < DIMV; i += 128) sct[i] = ct[b * DIMV + i] * (1.0f / LV);
    __syncthreads();
    float acc = b1[t];
    #pragma unroll 8
    for (int d = 0; d < DIMV; d++) acc += sct[d] * w1[d * GHID + t];
    shid[t] = gelu_f(acc);
    __syncthreads();
    for (int o = t; o < DIMV; o += 128) {
        float a2 = b2[o];
        #pragma unroll 8
        for (int g = 0; g < GHID; g++) a2 += shid[g] * w2[g * DIMV + o];
        gate[b * DIMV + o] = 1.0f / (1.0f + expf(-a2));
    }
}

// ---------------------------------------------------------------------------
// launch
// ---------------------------------------------------------------------------
extern "C" void kernel_launch(void* const* d_in, const int* in_sizes, int n_in,
                              void* d_out, int out_size) {
    const float* x      = (const float*)d_in[0];
    const float* ln1_g  = (const float*)d_in[1];
    const float* ln1_b  = (const float*)d_in[2];
    const float* w3     = (const float*)d_in[3];
    const float* b3     = (const float*)d_in[4];
    const float* w5     = (const float*)d_in[5];
    const float* b5     = (const float*)d_in[6];
    const float* w7     = (const float*)d_in[7];
    const float* b7     = (const float*)d_in[8];
    const float* wmix   = (const float*)d_in[9];
    const float* bmix   = (const float*)d_in[10];
    const float* cg_w1  = (const float*)d_in[11];
    const float* cg_b1  = (const float*)d_in[12];
    const float* cg_w2  = (const float*)d_in[13];
    const float* cg_b2  = (const float*)d_in[14];
    const float* wout   = (const float*)d_in[15];
    const float* bout   = (const float*)d_in[16];
    const float* ls1    = (const float*)d_in[17];
    const float* ln2_g  = (const float*)d_in[18];
    const float* ln2_b  = (const float*)d_in[19];
    const float* ffn_w1 = (const float*)d_in[20];
    const float* ffn_b1 = (const float*)d_in[21];
    const float* ffn_w2 = (const float*)d_in[22];
    const float* ffn_b2 = (const float*)d_in[23];
    const float* ls2    = (const float*)d_in[24];
    float* out = (float*)d_out;

    __half *p_mixg, *p_mixed2, *p_h2, *p_hid;
    __half *p_wmixT, *p_wout, *p_w1, *p_w2;
    float *p_x1, *p_ct, *p_gate;
    cudaGetSymbolAddress((void**)&p_mixg,   g_mixg_h);
    cudaGetSymbolAddress((void**)&p_mixed2, g_mixed2_h);
    cudaGetSymbolAddress((void**)&p_h2,     g_h2_h);
    cudaGetSymbolAddress((void**)&p_hid,    g_hid_h);
    cudaGetSymbolAddress((void**)&p_x1,     g_x1);
    cudaGetSymbolAddress((void**)&p_ct,     g_ct);
    cudaGetSymbolAddress((void**)&p_gate,   g_gate);
    cudaGetSymbolAddress((void**)&p_wmixT,  g_wmixT_h);
    cudaGetSymbolAddress((void**)&p_wout,   g_wout_h);
    cudaGetSymbolAddress((void**)&p_w1,     g_w1_h);
    cudaGetSymbolAddress((void**)&p_w2,     g_w2_h);

    cudaFuncSetAttribute((const void*)mma_gemm<0, false>, cudaFuncAttributeMaxDynamicSharedMemorySize, GEMM_SMEM);
    cudaFuncSetAttribute((const void*)mma_gemm<1, false>, cudaFuncAttributeMaxDynamicSharedMemorySize, GEMM_SMEM);
    cudaFuncSetAttribute((const void*)mma_gemm<2, false>, cudaFuncAttributeMaxDynamicSharedMemorySize, GEMM_SMEM);
    cudaFuncSetAttribute((const void*)mma_gemm<2, true>,  cudaFuncAttributeMaxDynamicSharedMemorySize, GEMM_SMEM);
    cudaFuncSetAttribute(ln_conv_kernel, cudaFuncAttributeMaxDynamicSharedMemorySize, LNCONV_SMEM);

    // 0) weight prep + ct zero
    transpose_h_kernel<<<dim3(DIMV / 32, DIMV / 32), dim3(32, 8)>>>(wmix, p_wmixT, DIMV, DIMV);
    wconv_all_kernel<<<(WOUT_N + 2 * W1_N) / 4 / 256, 256>>>(
        wout, ffn_w1, ffn_w2, p_wout, p_w1, p_w2);
    zero_kernel<<<(BV * DIMV + 255) / 256, 256>>>(p_ct, BV * DIMV);

    // 1) fused LN1 + conv + gelu -> fp16
    ln_conv_kernel<<<dim3(LV / CONV_L, BV), 256, LNCONV_SMEM>>>(
        x, ln1_g, ln1_b, w3, b3, w5, b5, w7, b7, p_mixg);

    // 2) mixed2 = mixg @ wmixT + bmix   (+ fused column-sum -> g_ct)
    mma_gemm<0, false><<<dim3(DIMV / 128, NROWS / 128), 256, GEMM_SMEM>>>(
        p_mixg, p_wmixT, bmix, p_mixed2, DIMV, DIMV, nullptr, nullptr, nullptr, p_ct);

    // 3) gate MLP (ct ready)
    gate_kernel<<<BV, 128>>>(p_ct, cg_w1, cg_b1, cg_w2, cg_b2, p_gate);

    // 4) x1 = x + ((mixed2*gate) @ wout + bout) * ls1   (gate folded into A)
    mma_gemm<2, true><<<dim3(DIMV / 128, NROWS / 128), 256, GEMM_SMEM>>>(
        p_mixed2, p_wout, bout, p_x1, DIMV, DIMV, x, ls1, p_gate, nullptr);

    // 5) LN2 -> fp16
    ln_kernel<<<NROWS, 128>>>(p_x1, ln2_g, ln2_b, p_h2);

    // 6) hid = gelu(h2 @ ffn_w1 + ffn_b1)
    mma_gemm<1, false><<<dim3(HIDV / 128, NROWS / 128), 256, GEMM_SMEM>>>(
        p_h2, p_w1, ffn_b1, p_hid, DIMV, HIDV, nullptr, nullptr, nullptr, nullptr);

    // 7) out = x1 + (hid @ ffn_w2 + ffn_b2) * ls2
    mma_gemm<2, false><<<dim3(DIMV / 128, NROWS / 128), 256, GEMM_SMEM>>>(
        p_hid, p_w2, ffn_b2, out, HIDV, DIMV, p_x1, ls2, nullptr, nullptr);
}

// round 16
// speedup vs baseline: 1.0472x; 1.0472x over previous
#include <cuda_runtime.h>
#include <cuda_fp16.h>
#include <math.h>
#include <stdint.h>

// ---------------------------------------------------------------------------
// Problem constants
// ---------------------------------------------------------------------------
#define DIMV 512
#define BV   16
#define LV   2048
#define NROWS (BV * LV)      // 32768
#define HIDV 2048
#define GHID 128
#define LN_EPS 1e-5f
#define LCH  16              // l-chunks for ct partials (LV/128)

// ---------------------------------------------------------------------------
// Scratch (device globals — no allocations allowed)
// ---------------------------------------------------------------------------
__device__ __half g_mixg_h  [(size_t)NROWS * DIMV];
__device__ __half g_mixed2_h[(size_t)NROWS * DIMV];
__device__ __half g_h2_h    [(size_t)NROWS * DIMV];
__device__ __half g_hid_h   [(size_t)NROWS * HIDV];
__device__ float g_x1   [(size_t)NROWS * DIMV];
__device__ float g_ctp  [LCH][BV][DIMV];                   // ct partial sums
__device__ float g_gate [BV * DIMV];
__device__ __half g_wmixT_h[DIMV * DIMV];          // [c][o]  (wmix.T)
__device__ __half g_wout_h [DIMV * DIMV];          // [k][m] as given
__device__ __half g_w1_h   [(size_t)DIMV * HIDV];  // [k][m] as given
__device__ __half g_w2_h   [(size_t)HIDV * DIMV];  // [k][m] as given

// ---------------------------------------------------------------------------
// Helpers
// ---------------------------------------------------------------------------
__device__ __forceinline__ uint32_t smem_u32(const void* p) {
    uint32_t a;
    asm("{ .reg .u64 t; cvta.to.shared.u64 t, %1; cvt.u32.u64 %0, t; }" : "=r"(a) : "l"(p));
    return a;
}
__device__ __forceinline__ void cp16(void* sdst, const void* gsrc) {
    uint32_t s = smem_u32(sdst);
    asm volatile("cp.async.cg.shared.global [%0], [%1], 16;" :: "r"(s), "l"(gsrc));
}
#define CP_COMMIT() asm volatile("cp.async.commit_group;" ::: "memory")
#define CP_WAIT(N)  asm volatile("cp.async.wait_group %0;" :: "n"(N) : "memory")

__device__ __forceinline__ void ldsm4(uint32_t* r, const void* p) {
    uint32_t a = smem_u32(p);
    asm volatile("ldmatrix.sync.aligned.m8n8.x4.shared.b16 {%0,%1,%2,%3}, [%4];"
        : "=r"(r[0]), "=r"(r[1]), "=r"(r[2]), "=r"(r[3]) : "r"(a));
}
__device__ __forceinline__ void ldsm4t(uint32_t* r, const void* p) {
    uint32_t a = smem_u32(p);
    asm volatile("ldmatrix.sync.aligned.m8n8.x4.trans.shared.b16 {%0,%1,%2,%3}, [%4];"
        : "=r"(r[0]), "=r"(r[1]), "=r"(r[2]), "=r"(r[3]) : "r"(a));
}
// fp16 mma with fp16 accumulators
__device__ __forceinline__ void mma16816h(uint32_t* c, const uint32_t* a, const uint32_t* b) {
    asm volatile("mma.sync.aligned.m16n8k16.row.col.f16.f16.f16.f16 "
        "{%0,%1}, {%2,%3,%4,%5}, {%6,%7}, {%0,%1};"
        : "+r"(c[0]), "+r"(c[1])
        : "r"(a[0]), "r"(a[1]), "r"(a[2]), "r"(a[3]), "r"(b[0]), "r"(b[1]));
}
__device__ __forceinline__ uint32_t hmul2u(uint32_t a, uint32_t b) {
    __half2 x = *reinterpret_cast<__half2*>(&a);
    __half2 y = *reinterpret_cast<__half2*>(&b);
    __half2 r = __hmul2(x, y);
    return *reinterpret_cast<uint32_t*>(&r);
}

__device__ __forceinline__ float gelu_f(float v) {
    return 0.5f * v * (1.0f + erff(v * 0.70710678118654752f));
}
__device__ __forceinline__ uint32_t pack_h2(float a, float b) {
    __half2 h = __floats2half2_rn(a, b);
    return *reinterpret_cast<uint32_t*>(&h);
}
__device__ __forceinline__ float2 unpack_h2(uint32_t u) {
    __half2 h = *reinterpret_cast<__half2*>(&u);
    return __half22float2(h);
}

// ---------------------------------------------------------------------------
// fp16 mma.sync GEMM (f16 acc): 128x128 tile, BK=32, 8 warps (4x2),
//   warp tile 32x64, 3-stage cp.async, 3 CTAs/SM.  (R13 champion config)
//   GATE: multiply A fragments by per-(batch,k) gate (fp16).
//   EPI 0: f16 out = acc + bias
//   EPI 1: f16 out = gelu(acc + bias)
//   EPI 2: f32 out = resid + (acc + bias) * ls
// ---------------------------------------------------------------------------
#define AS_STRIDE 40
#define BS_STRIDE 136
#define AS_STAGE  (128 * AS_STRIDE)
#define BS_STAGE  (32 * BS_STRIDE)
#define SGATE_OFF (3 * (AS_STAGE + BS_STAGE))          // half units
#define GEMM_SMEM ((SGATE_OFF + 512) * 2)              // 57856 bytes

template<int EPI, bool GATE>
__global__ void __launch_bounds__(256, 3)
mma_gemm(const __half* __restrict__ A, const __half* __restrict__ W,
         const float* __restrict__ bias, void* __restrict__ Cout, int K, int M,
         const float* __restrict__ resid, const float* __restrict__ ls,
         const float* __restrict__ gate) {
    extern __shared__ __half sm[];
    __half* As = sm;
    __half* Bs = sm + 3 * AS_STAGE;
    uint32_t* sgate = (uint32_t*)(sm + SGATE_OFF);

    int tid = threadIdx.x, wid = tid >> 5, lane = tid & 31;
    int wm = wid & 3, wn = wid >> 2;
    size_t rowBase = (size_t)blockIdx.y * 128;
    int colBase = blockIdx.x * 128;
    const __half* Abase = A + rowBase * (size_t)K;

    if (GATE) {
        int b = (int)(rowBase >> 11);
        if (tid < 256) {
            float g0 = gate[b * DIMV + tid * 2];
            float g1 = gate[b * DIMV + tid * 2 + 1];
            sgate[tid] = pack_h2(g0, g1);
        }
    }

    auto prefetch = [&](int cc, int st) {
        int k0 = cc << 5;
        __half* as = As + st * AS_STAGE;
        __half* bs = Bs + st * BS_STAGE;
        #pragma unroll
        for (int i = 0; i < 2; i++) {
            int q = (i << 8) + tid;
            int r = q >> 2, c = (q & 3) << 3;
            cp16(as + r * AS_STRIDE + c, Abase + (size_t)r * K + k0 + c);
            int r2 = q >> 4, c2 = (q & 15) << 3;
            cp16(bs + r2 * BS_STRIDE + c2, W + (size_t)(k0 + r2) * M + colBase + c2);
        }
    };

    uint32_t acc[2][8][2];
    #pragma unroll
    for (int mi = 0; mi < 2; mi++)
        #pragma unroll
        for (int nj = 0; nj < 8; nj++) { acc[mi][nj][0] = 0u; acc[mi][nj][1] = 0u; }

    int nch = K >> 5;
    prefetch(0, 0); CP_COMMIT();
    prefetch(1, 1); CP_COMMIT();

    int la = lane & 15, lb = lane >> 4;
    int tp = lane & 3;
    int st = 0, stw = 2;
    #pragma unroll 1
    for (int cc = 0; cc < nch; cc++) {
        CP_WAIT(1);
        __syncthreads();
        if (cc + 2 < nch) prefetch(cc + 2, stw);
        CP_COMMIT();

        __half* as = As + st * AS_STAGE;
        __half* bs = Bs + st * BS_STAGE;
        #pragma unroll
        for (int ks = 0; ks < 2; ks++) {
            uint32_t af[2][4], bf[4][4];
            #pragma unroll
            for (int mi = 0; mi < 2; mi++)
                ldsm4(af[mi], as + (wm * 32 + mi * 16 + la) * AS_STRIDE + ks * 16 + lb * 8);
            if (GATE) {
                uint32_t gp0 = sgate[cc * 16 + ks * 8 + tp];
                uint32_t gp1 = sgate[cc * 16 + ks * 8 + tp + 4];
                #pragma unroll
                for (int mi = 0; mi < 2; mi++) {
                    af[mi][0] = hmul2u(af[mi][0], gp0);
                    af[mi][1] = hmul2u(af[mi][1], gp0);
                    af[mi][2] = hmul2u(af[mi][2], gp1);
                    af[mi][3] = hmul2u(af[mi][3], gp1);
                }
            }
            #pragma unroll
            for (int ng = 0; ng < 4; ng++)
                ldsm4t(bf[ng], bs + (ks * 16 + la) * BS_STRIDE + wn * 64 + ng * 16 + lb * 8);
            #pragma unroll
            for (int mi = 0; mi < 2; mi++)
                #pragma unroll
                for (int nj = 0; nj < 8; nj++)
                    mma16816h(acc[mi][nj], af[mi], &bf[nj >> 1][(nj & 1) * 2]);
        }
        st = (st == 2) ? 0 : st + 1;
        stw = (stw == 2) ? 0 : stw + 1;
    }

    // ---- epilogue ----
    int tg = lane >> 2;
    #pragma unroll
    for (int mi = 0; mi < 2; mi++) {
        size_t r0 = rowBase + (size_t)(wm * 32 + mi * 16 + tg);
        size_t r1 = r0 + 8;
        #pragma unroll
        for (int nj = 0; nj < 8; nj++) {
            int col = colBase + wn * 64 + nj * 8 + tp * 2;
            float2 v0 = unpack_h2(acc[mi][nj][0]);
            float2 v1 = unpack_h2(acc[mi][nj][1]);
            float b0 = __ldg(&bias[col]), b1 = __ldg(&bias[col + 1]);
            if (EPI == 0 || EPI == 1) {
                float a0 = v0.x + b0, a1 = v0.y + b1;
                float a2 = v1.x + b0, a3 = v1.y + b1;
                if (EPI == 1) { a0 = gelu_f(a0); a1 = gelu_f(a1); a2 = gelu_f(a2); a3 = gelu_f(a3); }
                __half* op = (__half*)Cout;
                *(uint32_t*)(op + r0 * M + col) = pack_h2(a0, a1);
                *(uint32_t*)(op + r1 * M + col) = pack_h2(a2, a3);
            } else {
                float s0 = __ldg(&ls[col]), s1 = __ldg(&ls[col + 1]);
                float* op = (float*)Cout;
                float2 rr0 = *(const float2*)(resid + r0 * M + col);
                float2 rr1 = *(const float2*)(resid + r1 * M + col);
                float2 o0 = make_float2(rr0.x + (v0.x + b0) * s0, rr0.y + (v0.y + b1) * s1);
                float2 o1 = make_float2(rr1.x + (v1.x + b0) * s0, rr1.y + (v1.y + b1) * s1);
                *(float2*)(op + r0 * M + col) = o0;
                *(float2*)(op + r1 * M + col) = o1;
            }
        }
    }
}

// ---------------------------------------------------------------------------
// Standalone LayerNorm (LN2): fp32 in -> fp16 out, 1 block/row.
// ---------------------------------------------------------------------------
__device__ __forceinline__ void block_reduce_2(float& s, float& sq) {
    #pragma unroll
    for (int off = 16; off > 0; off >>= 1) {
        s  += __shfl_down_sync(0xffffffffu, s,  off);
        sq += __shfl_down_sync(0xffffffffu, sq, off);
    }
    __shared__ float sh[8];
    int w = threadIdx.x >> 5, lane = threadIdx.x & 31;
    if (lane == 0) { sh[w] = s; sh[4 + w] = sq; }
    __syncthreads();
    if (threadIdx.x < 32) {
        float a = (lane < 4) ? sh[lane] : 0.f;
        float b = (lane < 4) ? sh[4 + lane] : 0.f;
        #pragma unroll
        for (int off = 2; off > 0; off >>= 1) {
            a += __shfl_down_sync(0xffffffffu, a, off);
            b += __shfl_down_sync(0xffffffffu, b, off);
        }
        if (lane == 0) { sh[0] = a; sh[1] = b; }
    }
    __syncthreads();
    s = sh[0]; sq = sh[1];
}

__global__ void ln_kernel(const float* __restrict__ x, const float* __restrict__ g,
                          const float* __restrict__ b, __half* __restrict__ out) {
    size_t row = blockIdx.x;
    float4 v = ((const float4*)(x + row * DIMV))[threadIdx.x];
    float s  = v.x + v.y + v.z + v.w;
    float sq = v.x * v.x + v.y * v.y + v.z * v.z + v.w * v.w;
    block_reduce_2(s, sq);
    float mu  = s * (1.0f / DIMV);
    float var = sq * (1.0f / DIMV) - mu * mu;
    float r   = rsqrtf(var + LN_EPS);
    float4 gg = ((const float4*)g)[threadIdx.x];
    float4 bb = ((const float4*)b)[threadIdx.x];
    float o0 = (v.x - mu) * r * gg.x + bb.x;
    float o1 = (v.y - mu) * r * gg.y + bb.y;
    float o2 = (v.z - mu) * r * gg.z + bb.z;
    float o3 = (v.w - mu) * r * gg.w + bb.w;
    *(uint2*)(out + row * DIMV + threadIdx.x * 4) = make_uint2(pack_h2(o0, o1), pack_h2(o2, o3));
}

// ---------------------------------------------------------------------------
// Fused LN1 + depthwise conv (k=3,5,7 avg) + GELU -> fp16.
// 512 threads: phase 1 = 16 warps LN rows; phase 2 = 256 channel-pairs x 2 l-halves.
// ---------------------------------------------------------------------------
#define CONV_L 128
#define CHALO 3
#define CROWS (CONV_L + 2 * CHALO)              // 134
#define LNCONV_SMEM (CROWS * DIMV * 2)          // 137216 bytes

__global__ void __launch_bounds__(512, 1)
ln_conv_kernel(const float* __restrict__ x,
               const float* __restrict__ g, const float* __restrict__ bb_,
               const float* __restrict__ w3, const float* __restrict__ b3,
               const float* __restrict__ w5, const float* __restrict__ b5,
               const float* __restrict__ w7, const float* __restrict__ b7,
               __half* __restrict__ out) {
    extern __shared__ __half tile[];            // [CROWS][DIMV]
    int tid = threadIdx.x, wid = tid >> 5, lane = tid & 31;
    int l0 = blockIdx.x * CONV_L;
    int b  = blockIdx.y;

    // ---- Phase 1: LN rows into smem (16 warps, one row per warp, rr) ----
    for (int r = wid; r < CROWS; r += 16) {
        int l = l0 - CHALO + r;
        if (l < 0 || l >= LV) continue;
        const float4* xr = (const float4*)(x + ((size_t)(b * LV + l) << 9));
        float4 v[4];
        float s = 0.f, sq = 0.f;
        #pragma unroll
        for (int i = 0; i < 4; i++) {
            v[i] = xr[lane + 32 * i];
            s  += v[i].x + v[i].y + v[i].z + v[i].w;
            sq += v[i].x * v[i].x + v[i].y * v[i].y + v[i].z * v[i].z + v[i].w * v[i].w;
        }
        #pragma unroll
        for (int off = 16; off > 0; off >>= 1) {
            s  += __shfl_xor_sync(0xffffffffu, s,  off);
            sq += __shfl_xor_sync(0xffffffffu, sq, off);
        }
        float mu  = s * (1.0f / DIMV);
        float var = sq * (1.0f / DIMV) - mu * mu;
        float rs  = rsqrtf(var + LN_EPS);
        #pragma unroll
        for (int i = 0; i < 4; i++) {
            int c = (lane + 32 * i) * 4;
            float4 gg = ((const float4*)g)[lane + 32 * i];
            float4 bv = ((const float4*)bb_)[lane + 32 * i];
            float o0 = (v[i].x - mu) * rs * gg.x + bv.x;
            float o1 = (v[i].y - mu) * rs * gg.y + bv.y;
            float o2 = (v[i].z - mu) * rs * gg.z + bv.z;
            float o3 = (v[i].w - mu) * rs * gg.w + bv.w;
            *(uint2*)&tile[r * DIMV + c] = make_uint2(pack_h2(o0, o1), pack_h2(o2, o3));
        }
    }
    __syncthreads();

    // ---- Phase 2: conv + gelu. Thread owns channel pair, half the l-range ----
    int c   = (tid & 255) * 2;
    int il0 = (tid >> 8) * (CONV_L / 2);
    float t0[7], t1[7];
    #pragma unroll
    for (int j = 0; j < 7; j++) { t0[j] = w7[c * 7 + j]; t1[j] = w7[(c + 1) * 7 + j]; }
    #pragma unroll
    for (int j = 1; j <= 5; j++) { t0[j] += w5[c * 5 + (j - 1)]; t1[j] += w5[(c + 1) * 5 + (j - 1)]; }
    #pragma unroll
    for (int j = 2; j <= 4; j++) { t0[j] += w3[c * 3 + (j - 2)]; t1[j] += w3[(c + 1) * 3 + (j - 2)]; }
    float base0 = b3[c] + b5[c] + b7[c];
    float base1 = b3[c + 1] + b5[c + 1] + b7[c + 1];

    #pragma unroll 2
    for (int ii = 0; ii < CONV_L / 2; ii++) {
        int il = il0 + ii;
        int l = l0 + il;
        float a0 = base0, a1 = base1;
        #pragma unroll
        for (int j = 0; j < 7; j++) {
            int ll = l + j - 3;
            if (ll >= 0 && ll < LV) {
                uint32_t u = *(uint32_t*)&tile[(il + j) * DIMV + c];
                float2 hv = unpack_h2(u);
                a0 += t0[j] * hv.x;
                a1 += t1[j] * hv.y;
            }
        }
        *(uint32_t*)(out + ((size_t)(b * LV + l) << 9) + c) =
            pack_h2(gelu_f(a0 * (1.0f / 3.0f)), gelu_f(a1 * (1.0f / 3.0f)));
    }
}

// ---------------------------------------------------------------------------
// Weight prep
// ---------------------------------------------------------------------------
__global__ void transpose_h_kernel(const float* __restrict__ in, __half* __restrict__ out,
                                   int R, int C) {
    __shared__ float t[32][33];
    int c0 = blockIdx.x * 32, r0 = blockIdx.y * 32;
    int tx = threadIdx.x, ty = threadIdx.y;
    #pragma unroll
    for (int i = 0; i < 32; i += 8)
        t[ty + i][tx] = in[(size_t)(r0 + ty + i) * C + c0 + tx];
    __syncthreads();
    #pragma unroll
    for (int i = 0; i < 32; i += 8)
        out[(size_t)(c0 + ty + i) * R + r0 + tx] = __float2half_rn(t[tx][ty + i]);
}

#define WOUT_N (DIMV * DIMV)          // 262144
#define W1_N   (DIMV * HIDV)          // 1048576
__global__ void wconv_all_kernel(const float* __restrict__ wout, const float* __restrict__ w1,
                                 const float* __restrict__ w2,
                                 __half* __restrict__ o_wout, __half* __restrict__ o_w1,
                                 __half* __restrict__ o_w2) {
    size_t i = ((size_t)blockIdx.x * 256 + threadIdx.x) * 4;
    const float* src; __half* dst; size_t off;
    if (i < WOUT_N)              { src = wout; dst = o_wout; off = i; }
    else if (i < WOUT_N + W1_N)  { src = w1;   dst = o_w1;   off = i - WOUT_N; }
    else                         { src = w2;   dst = o_w2;   off = i - WOUT_N - W1_N; }
    float4 v = *(const float4*)(src + off);
    *(uint2*)(dst + off) = make_uint2(pack_h2(v.x, v.y), pack_h2(v.z, v.w));
}

// ---------------------------------------------------------------------------
// Channel token partials (no atomics)
// ---------------------------------------------------------------------------
__global__ void ct_partial_kernel(const __half* __restrict__ m2,
                                  float* __restrict__ ctp) {
    int o  = blockIdx.x * 128 + threadIdx.x;
    int ly = blockIdx.y;
    int b  = blockIdx.z;
    const __half* p = m2 + ((size_t)b * LV + ly * 128) * DIMV + o;
    float s = 0.f;
    #pragma unroll 8
    for (int l = 0; l < 128; l++) s += __half2float(__ldg(p + (size_t)l * DIMV));
    ctp[((size_t)ly * BV + b) * DIMV + o] = s;
}

// ---------------------------------------------------------------------------
// gate MLP (folds 16-way partial reduction)
// ---------------------------------------------------------------------------
__global__ void gate_kernel(const float* __restrict__ ctp,
                            const float* __restrict__ w1, const float* __restrict__ b1,
                            const float* __restrict__ w2, const float* __restrict__ b2,
                            float* __restrict__ gate) {
    __shared__ float sct[DIMV];
    __shared__ float shid[GHID];
    int b = blockIdx.x, t = threadIdx.x;
    for (int i = t; i < DIMV; i += 128) {
        float s = 0.f;
        #pragma unroll
        for (int ly = 0; ly < LCH; ly++)
            s += ctp[((size_t)ly * BV + b) * DIMV + i];
        sct[i] = s * (1.0f / LV);
    }
    __syncthreads();
    float acc = b1[t];
    #pragma unroll 8
    for (int d = 0; d < DIMV; d++) acc += sct[d] * w1[d * GHID + t];
    shid[t] = gelu_f(acc);
    __syncthreads();
    for (int o = t; o < DIMV; o += 128) {
        float a2 = b2[o];
        #pragma unroll 8
        for (int g = 0; g < GHID; g++) a2 += shid[g] * w2[g * DIMV + o];
        gate[b * DIMV + o] = 1.0f / (1.0f + expf(-a2));
    }
}

// ---------------------------------------------------------------------------
// launch
// ---------------------------------------------------------------------------
extern "C" void kernel_launch(void* const* d_in, const int* in_sizes, int n_in,
                              void* d_out, int out_size) {
    const float* x      = (const float*)d_in[0];
    const float* ln1_g  = (const float*)d_in[1];
    const float* ln1_b  = (const float*)d_in[2];
    const float* w3     = (const float*)d_in[3];
    const float* b3     = (const float*)d_in[4];
    const float* w5     = (const float*)d_in[5];
    const float* b5     = (const float*)d_in[6];
    const float* w7     = (const float*)d_in[7];
    const float* b7     = (const float*)d_in[8];
    const float* wmix   = (const float*)d_in[9];
    const float* bmix   = (const float*)d_in[10];
    const float* cg_w1  = (const float*)d_in[11];
    const float* cg_b1  = (const float*)d_in[12];
    const float* cg_w2  = (const float*)d_in[13];
    const float* cg_b2  = (const float*)d_in[14];
    const float* wout   = (const float*)d_in[15];
    const float* bout   = (const float*)d_in[16];
    const float* ls1    = (const float*)d_in[17];
    const float* ln2_g  = (const float*)d_in[18];
    const float* ln2_b  = (const float*)d_in[19];
    const float* ffn_w1 = (const float*)d_in[20];
    const float* ffn_b1 = (const float*)d_in[21];
    const float* ffn_w2 = (const float*)d_in[22];
    const float* ffn_b2 = (const float*)d_in[23];
    const float* ls2    = (const float*)d_in[24];
    float* out = (float*)d_out;

    __half *p_mixg, *p_mixed2, *p_h2, *p_hid;
    __half *p_wmixT, *p_wout, *p_w1, *p_w2;
    float *p_x1, *p_ctp, *p_gate;
    cudaGetSymbolAddress((void**)&p_mixg,   g_mixg_h);
    cudaGetSymbolAddress((void**)&p_mixed2, g_mixed2_h);
    cudaGetSymbolAddress((void**)&p_h2,     g_h2_h);
    cudaGetSymbolAddress((void**)&p_hid,    g_hid_h);
    cudaGetSymbolAddress((void**)&p_x1,     g_x1);
    cudaGetSymbolAddress((void**)&p_ctp,    g_ctp);
    cudaGetSymbolAddress((void**)&p_gate,   g_gate);
    cudaGetSymbolAddress((void**)&p_wmixT,  g_wmixT_h);
    cudaGetSymbolAddress((void**)&p_wout,   g_wout_h);
    cudaGetSymbolAddress((void**)&p_w1,     g_w1_h);
    cudaGetSymbolAddress((void**)&p_w2,     g_w2_h);

    cudaFuncSetAttribute((const void*)mma_gemm<0, false>, cudaFuncAttributeMaxDynamicSharedMemorySize, GEMM_SMEM);
    cudaFuncSetAttribute((const void*)mma_gemm<1, false>, cudaFuncAttributeMaxDynamicSharedMemorySize, GEMM_SMEM);
    cudaFuncSetAttribute((const void*)mma_gemm<2, false>, cudaFuncAttributeMaxDynamicSharedMemorySize, GEMM_SMEM);
    cudaFuncSetAttribute((const void*)mma_gemm<2, true>,  cudaFuncAttributeMaxDynamicSharedMemorySize, GEMM_SMEM);
    cudaFuncSetAttribute(ln_conv_kernel, cudaFuncAttributeMaxDynamicSharedMemorySize, LNCONV_SMEM);

    // 0) weight prep
    transpose_h_kernel<<<dim3(DIMV / 32, DIMV / 32), dim3(32, 8)>>>(wmix, p_wmixT, DIMV, DIMV);
    wconv_all_kernel<<<(WOUT_N + 2 * W1_N) / 4 / 256, 256>>>(
        wout, ffn_w1, ffn_w2, p_wout, p_w1, p_w2);

    // 1) fused LN1 + conv + gelu -> fp16   (512 threads)
    ln_conv_kernel<<<dim3(LV / CONV_L, BV), 512, LNCONV_SMEM>>>(
        x, ln1_g, ln1_b, w3, b3, w5, b5, w7, b7, p_mixg);

    // 2) mixed2 = mixg @ wmixT + bmix
    mma_gemm<0, false><<<dim3(DIMV / 128, NROWS / 128), 256, GEMM_SMEM>>>(
        p_mixg, p_wmixT, bmix, p_mixed2, DIMV, DIMV, nullptr, nullptr, nullptr);

    // 3) channel-token partials + gate MLP
    ct_partial_kernel<<<dim3(DIMV / 128, LCH, BV), 128>>>(p_mixed2, p_ctp);
    gate_kernel<<<BV, 128>>>(p_ctp, cg_w1, cg_b1, cg_w2, cg_b2, p_gate);

    // 4) x1 = x + ((mixed2*gate) @ wout + bout) * ls1   (gate folded into A)
    mma_gemm<2, true><<<dim3(DIMV / 128, NROWS / 128), 256, GEMM_SMEM>>>(
        p_mixed2, p_wout, bout, p_x1, DIMV, DIMV, x, ls1, p_gate);

    // 5) LN2 -> fp16
    ln_kernel<<<NROWS, 128>>>(p_x1, ln2_g, ln2_b, p_h2);

    // 6) hid = gelu(h2 @ ffn_w1 + ffn_b1)
    mma_gemm<1, false><<<dim3(HIDV / 128, NROWS / 128), 256, GEMM_SMEM>>>(
        p_h2, p_w1, ffn_b1, p_hid, DIMV, HIDV, nullptr, nullptr, nullptr);

    // 7) out = x1 + (hid @ ffn_w2 + ffn_b2) * ls2
    mma_gemm<2, false><<<dim3(DIMV / 128, NROWS / 128), 256, GEMM_SMEM>>>(
        p_hid, p_w2, ffn_b2, out, HIDV, DIMV, p_x1, ls2, nullptr);
}